// round 4
// baseline (speedup 1.0000x reference)
#include <cuda_runtime.h>
#include <cstdint>

#define N2    361
#define NTHR  384
#define NBITS 8192
#define NWORDS (NBITS / 32)
#define GMAX  32
#define NEGV  (-1000000000.0f)
#define I32MIN_V (-2147483647 - 1)

__global__ __launch_bounds__(NTHR, 5)
void go_mask_kernel(const float* __restrict__ logits,
                    const int* __restrict__ legal,      // bool serialized as int32
                    const int* __restrict__ player,
                    const int* __restrict__ cur_hash,
                    const int* __restrict__ hist,
                    const int* __restrict__ move_count,
                    const int* __restrict__ ZposT,
                    const int* __restrict__ sgi,
                    const int* __restrict__ sp,
                    const int* __restrict__ gp,
                    const int* __restrict__ cap,
                    float* __restrict__ out)
{
    __shared__ int      sh_hist[N2];      // this board's history
    __shared__ unsigned sh_bits[NWORDS];  // bloom bitset (8192 bits)
    __shared__ int      sh_gx[GMAX];      // per-local-group XOR

    const int b = blockIdx.x;
    const int t = threadIdx.x;

    // ---- front-load every streaming read (latency overlapped with setup) ----
    const int pl = player[b];
    const int ch = cur_hash[b];

    int   h_val = 0;
    int4  c4    = make_int4(-1, -1, -1, -1);
    float lg    = 0.0f;
    int   lgl   = 0;
    int   z_e   = 0, z_m = 0;

    const size_t idx = (size_t)b * N2 + t;
    if (t < N2) {
        h_val = hist[idx];
        c4    = *reinterpret_cast<const int4*>(cap + idx * 4);
        lg    = logits[idx];
        lgl   = legal[idx];
        z_e   = ZposT[t];                                    // empty row (L2-hot)
        z_m   = ZposT[(pl == 0 ? 1 : 2) * N2 + t];           // mover's row
    }

    int mc = move_count[b];
    if (mc < 0)  mc = 0;
    if (mc > N2) mc = N2;

    // zero the bloom
    if (t < NWORDS) sh_bits[t] = 0u;
    if (t < N2)     sh_hist[t] = h_val;

    __syncthreads();

    // ---- phase 2 (parallel): bloom insert (t<361) + group XORs (t>=361) ----
    if (t < N2) {
        int  key;
        bool ins = true;
        if (t < mc)       key = h_val;
        else if (t == mc) key = I32MIN_V;   // sentinel (t<N2 => mc<N2)
        else              ins = false;
        if (ins) {
            const unsigned h  = (unsigned)key * 2654435761u;
            const unsigned b1 = h & (NBITS - 1);
            const unsigned b2 = (h >> 13) & (NBITS - 1);
            atomicOr(&sh_bits[b1 >> 5], 1u << (b1 & 31));
            atomicOr(&sh_bits[b2 >> 5], 1u << (b2 & 31));
        }
    } else {
        const int g0 = gp[b];
        int nG = gp[b + 1] - g0;
        if (nG > GMAX) nG = GMAX;
        const int opp_row = (2 - pl) * N2;   // row 1 + (1 - pl)
        for (int g = t - N2; g < nG; g += (NTHR - N2)) {
            const int s0 = sp[g0 + g];
            const int s1 = sp[g0 + g + 1];
            int acc = 0;
            for (int s = s0; s < s1; ++s) {
                int si = sgi[s];
                si = si < 0 ? 0 : (si >= N2 ? N2 - 1 : si);
                acc ^= ZposT[opp_row + si] ^ ZposT[si];
            }
            sh_gx[g] = acc;
        }
    }
    __syncthreads();

    // ---- phase 3: candidate hash + membership + output ----
    if (t < N2) {
        int cd = 0;
        {
            int c;
            c = c4.x; if (c >= 0) cd ^= sh_gx[c >= GMAX ? GMAX - 1 : c];
            c = c4.y; if (c >= 0) cd ^= sh_gx[c >= GMAX ? GMAX - 1 : c];
            c = c4.z; if (c >= 0) cd ^= sh_gx[c >= GMAX ? GMAX - 1 : c];
            c = c4.w; if (c >= 0) cd ^= sh_gx[c >= GMAX ? GMAX - 1 : c];
        }

        const int cand = ch ^ (z_e ^ z_m) ^ cd;

        const unsigned h  = (unsigned)cand * 2654435761u;
        const unsigned b1 = h & (NBITS - 1);
        const unsigned b2 = (h >> 13) & (NBITS - 1);
        const bool maybe = (((sh_bits[b1 >> 5] >> (b1 & 31)) &
                             (sh_bits[b2 >> 5] >> (b2 & 31))) & 1u) != 0u;

        bool rep = false;
        if (maybe) {
            if (mc < N2 && cand == I32MIN_V) {
                rep = true;                       // sentinel in masked multiset
            } else {
                for (int j = 0; j < mc; ++j) {
                    if (sh_hist[j] == cand) { rep = true; break; }
                }
            }
        }

        out[idx] = ((lgl != 0) & !rep) ? lg : NEGV;
    }
}

extern "C" void kernel_launch(void* const* d_in, const int* in_sizes, int n_in,
                              void* d_out, int out_size)
{
    const float* logits = (const float*)d_in[0];
    const int*   legal  = (const int*)d_in[1];
    const int*   player = (const int*)d_in[2];
    const int*   chash  = (const int*)d_in[3];
    const int*   hist   = (const int*)d_in[4];
    const int*   mcnt   = (const int*)d_in[5];
    const int*   zpos   = (const int*)d_in[6];
    const int*   sgi    = (const int*)d_in[7];
    const int*   sp     = (const int*)d_in[8];
    const int*   gp     = (const int*)d_in[9];
    const int*   cap    = (const int*)d_in[10];
    float*       out    = (float*)d_out;

    const int B = in_sizes[2];  // current_player has B elements

    go_mask_kernel<<<B, NTHR>>>(logits, legal, player, chash, hist, mcnt,
                                zpos, sgi, sp, gp, cap, out);
}

// round 5
// speedup vs baseline: 1.1831x; 1.1831x over previous
#include <cuda_runtime.h>
#include <cstdint>

#define N2     361
#define NTHR   384
#define NBITS  32768
#define NWORDS (NBITS / 32)          // 1024
#define GX     16
#define NEGV   (-1000000000.0f)
#define I32MIN_V (-2147483647 - 1)
#define RMAX   (16384 * 8)
#define GRID2  444                   // 148 SMs * 3 blocks

__device__ int g_gxor[RMAX];

// ---- kernel 1: per-group XOR of (z_opp ^ z_empty) over the group's stones ----
__global__ __launch_bounds__(256)
void group_xor_kernel(const int* __restrict__ player,
                      const int* __restrict__ sgi,
                      const int* __restrict__ sp,
                      const int* __restrict__ ZposT,
                      int R, int G)
{
    const int r = blockIdx.x * blockDim.x + threadIdx.x;
    if (r >= R) return;
    const int pl  = player[r / G];
    const int opp = (2 - pl) * N2;     // Zobrist row 1 + (1 - pl)
    const int s0 = sp[r], s1 = sp[r + 1];
    int acc = 0;
    for (int s = s0; s < s1; ++s) {
        int si = sgi[s];
        si = si < 0 ? 0 : (si >= N2 ? N2 - 1 : si);
        acc ^= ZposT[opp + si] ^ ZposT[si];
    }
    g_gxor[r] = acc;
}

// ---- kernel 2: persistent blocks, 1-deep board pipeline ----
__global__ __launch_bounds__(NTHR, 3)
void board_kernel(const float* __restrict__ logits,
                  const int* __restrict__ legal,      // bool as int32
                  const int* __restrict__ player,
                  const int* __restrict__ cur_hash,
                  const int* __restrict__ hist,
                  const int* __restrict__ move_count,
                  const int* __restrict__ ZposT,
                  const int* __restrict__ gp,
                  const int* __restrict__ cap,
                  float* __restrict__ out,
                  int B, int G)
{
    __shared__ int      sh_hist[N2];
    __shared__ unsigned sh_bits[2][NWORDS];   // double-buffered bloom
    __shared__ int      sh_gx[GX];

    const int t = threadIdx.x;

    // loop-invariant Zobrist rows
    int z_e = 0, z_b = 0, z_w = 0;
    if (t < N2) { z_e = ZposT[t]; z_b = ZposT[N2 + t]; z_w = ZposT[2 * N2 + t]; }

    // zero both bloom buffers once
    for (int i = t; i < 2 * NWORDS; i += NTHR) ((unsigned*)sh_bits)[i] = 0u;

    int b = blockIdx.x;

    // prologue prefetch (board b)
    int  c_pl = 0, c_ch = 0, c_mc = 0, c_h = 0, c_lgl = 0, c_gx = 0;
    float c_lg = 0.0f;
    int4  c_c4 = make_int4(-1, -1, -1, -1);
    if (b < B) {
        c_pl = player[b]; c_ch = cur_hash[b]; c_mc = move_count[b];
        const size_t idx = (size_t)b * N2 + t;
        if (t < N2) {
            c_h   = hist[idx];
            c_c4  = *reinterpret_cast<const int4*>(cap + idx * 4);
            c_lg  = logits[idx];
            c_lgl = legal[idx];
        }
        if (t < G) c_gx = g_gxor[gp[b] + t];
    }

    int p = 0;
    for (; b < B; b += gridDim.x) {
        __syncthreads();   // sync A: previous phase-3 done with shared

        // ---- prefetch board b + gridDim.x (overlaps phase2+phase3) ----
        const int nb = b + gridDim.x;
        int  n_pl = 0, n_ch = 0, n_mc = 0, n_h = 0, n_lgl = 0, n_gx = 0;
        float n_lg = 0.0f;
        int4  n_c4 = make_int4(-1, -1, -1, -1);
        if (nb < B) {
            n_pl = player[nb]; n_ch = cur_hash[nb]; n_mc = move_count[nb];
            const size_t nidx = (size_t)nb * N2 + t;
            if (t < N2) {
                n_h   = hist[nidx];
                n_c4  = *reinterpret_cast<const int4*>(cap + nidx * 4);
                n_lg  = logits[nidx];
                n_lgl = legal[nidx];
            }
            if (t < G) n_gx = g_gxor[gp[nb] + t];
        }

        // ---- phase 2: publish shared state + bloom insert (buffer p) ----
        int mc = c_mc; if (mc < 0) mc = 0; if (mc > N2) mc = N2;
        if (t < N2) sh_hist[t] = c_h;
        if (t < G && t < GX) sh_gx[t] = c_gx;
        // zero the OTHER buffer for the next iteration (safe: prior reader done)
        for (int i = t; i < NWORDS; i += NTHR) sh_bits[1 - p][i] = 0u;
        if (t < N2) {
            int  key;
            bool ins = true;
            if (t < mc)       key = c_h;
            else if (t == mc) key = I32MIN_V;     // sentinel (t<N2 => mc<N2)
            else              ins = false;
            if (ins) {
                const unsigned h  = (unsigned)key * 2654435761u;
                const unsigned b1 = h & (NBITS - 1);
                const unsigned b2 = (h >> 15) & (NBITS - 1);
                atomicOr(&sh_bits[p][b1 >> 5], 1u << (b1 & 31));
                atomicOr(&sh_bits[p][b2 >> 5], 1u << (b2 & 31));
            }
        }
        __syncthreads();   // sync B: bloom ready

        // ---- phase 3: candidate + membership + output ----
        if (t < N2) {
            int cd = 0, c;
            c = c_c4.x; if (c >= 0) cd ^= sh_gx[c & (GX - 1)];
            c = c_c4.y; if (c >= 0) cd ^= sh_gx[c & (GX - 1)];
            c = c_c4.z; if (c >= 0) cd ^= sh_gx[c & (GX - 1)];
            c = c_c4.w; if (c >= 0) cd ^= sh_gx[c & (GX - 1)];

            const int z_m  = (c_pl == 0) ? z_b : z_w;
            const int cand = c_ch ^ (z_e ^ z_m) ^ cd;

            const unsigned h  = (unsigned)cand * 2654435761u;
            const unsigned b1 = h & (NBITS - 1);
            const unsigned b2 = (h >> 15) & (NBITS - 1);
            const bool maybe = (((sh_bits[p][b1 >> 5] >> (b1 & 31)) &
                                 (sh_bits[p][b2 >> 5] >> (b2 & 31))) & 1u) != 0u;

            bool rep = false;
            if (maybe) {
                if (mc < N2 && cand == I32MIN_V) {
                    rep = true;                       // sentinel in masked multiset
                } else {
                    for (int j = 0; j < mc; ++j) {
                        if (sh_hist[j] == cand) { rep = true; break; }
                    }
                }
            }
            out[(size_t)b * N2 + t] = ((c_lgl != 0) & !rep) ? c_lg : NEGV;
        }

        // rotate pipeline registers
        c_pl = n_pl; c_ch = n_ch; c_mc = n_mc; c_h = n_h;
        c_lgl = n_lgl; c_gx = n_gx; c_lg = n_lg; c_c4 = n_c4;
        p ^= 1;
    }
}

extern "C" void kernel_launch(void* const* d_in, const int* in_sizes, int n_in,
                              void* d_out, int out_size)
{
    const float* logits = (const float*)d_in[0];
    const int*   legal  = (const int*)d_in[1];
    const int*   player = (const int*)d_in[2];
    const int*   chash  = (const int*)d_in[3];
    const int*   hist   = (const int*)d_in[4];
    const int*   mcnt   = (const int*)d_in[5];
    const int*   zpos   = (const int*)d_in[6];
    const int*   sgi    = (const int*)d_in[7];
    const int*   sp     = (const int*)d_in[8];
    const int*   gp     = (const int*)d_in[9];
    const int*   cap    = (const int*)d_in[10];
    float*       out    = (float*)d_out;

    const int B = in_sizes[2];           // current_player: B elements
    const int R = in_sizes[8] - 1;       // stone_global_pointer: R+1
    const int G = R / B;                 // groups per board (uniform)

    group_xor_kernel<<<(R + 255) / 256, 256>>>(player, sgi, sp, zpos, R, G);
    board_kernel<<<GRID2, NTHR>>>(logits, legal, player, chash, hist, mcnt,
                                  zpos, gp, cap, out, B, G);
}

// round 6
// speedup vs baseline: 1.6099x; 1.3608x over previous
#include <cuda_runtime.h>
#include <cstdint>

#define N2      361
#define NTHR    384
#define TSLOTS  1024
#define OVF_CAP 48
#define GX      16
#define NEGV    (-1000000000.0f)
#define I32MIN_V (-2147483647 - 1)
#define RMAX    (16384 * 8)
#define GRID2   (148 * 4)

__device__ int g_gxor[RMAX];

// ---- kernel 1: per-group XOR of (z_opp ^ z_empty) over the group's stones ----
__global__ __launch_bounds__(256)
void group_xor_kernel(const int* __restrict__ player,
                      const int* __restrict__ sgi,
                      const int* __restrict__ sp,
                      const int* __restrict__ ZposT,
                      int R, int G)
{
    const int r = blockIdx.x * blockDim.x + threadIdx.x;
    if (r >= R) return;
    const int pl  = player[r / G];
    const int opp = (2 - pl) * N2;     // Zobrist row 1 + (1 - pl)
    const int s0 = sp[r], s1 = sp[r + 1];
    int acc = 0;
    for (int s = s0; s < s1; ++s) {
        int si = sgi[s];
        si = si < 0 ? 0 : (si >= N2 ? N2 - 1 : si);
        acc ^= ZposT[opp + si] ^ ZposT[si];
    }
    g_gxor[r] = acc;
}

// ---- kernel 2: persistent blocks, exact hash table, 1-deep board pipeline ----
__global__ __launch_bounds__(NTHR, 4)
void board_kernel(const float* __restrict__ logits,
                  const int* __restrict__ legal,      // bool as int32
                  const int* __restrict__ player,
                  const int* __restrict__ cur_hash,
                  const int* __restrict__ hist,
                  const int* __restrict__ move_count,
                  const int* __restrict__ ZposT,
                  const int* __restrict__ gp,
                  const int* __restrict__ cap,
                  float* __restrict__ out,
                  int B, int G)
{
    __shared__ int sh_tab[2][TSLOTS];     // open-addressing table (double-buffered)
    __shared__ int sh_ovf[2][OVF_CAP];    // overflow keys
    __shared__ int sh_ovf_n[2];
    __shared__ int sh_hist[N2];           // safety fallback only
    __shared__ int sh_gx[GX];

    const int t = threadIdx.x;

    // loop-invariant placement deltas
    int zd_b = 0, zd_w = 0;
    if (t < N2) {
        const int ze = ZposT[t];
        zd_b = ze ^ ZposT[N2 + t];
        zd_w = ze ^ ZposT[2 * N2 + t];
    }

    // one-time init
    for (int i = t; i < 2 * TSLOTS; i += NTHR) ((int*)sh_tab)[i] = -1;
    if (t < 2)  sh_ovf_n[t] = 0;
    if (t < GX) sh_gx[t] = 0;

    int b = blockIdx.x;

    // prologue prefetch (board b)
    int  c_pl = 0, c_ch = 0, c_mc = 0, c_h = 0, c_lgl = 0, c_gx = 0;
    float c_lg = 0.0f;
    int4  c_c4 = make_int4(-1, -1, -1, -1);
    if (b < B) {
        c_pl = player[b]; c_ch = cur_hash[b]; c_mc = move_count[b];
        const size_t idx = (size_t)b * N2 + t;
        if (t < N2) {
            c_h   = hist[idx];
            c_c4  = *reinterpret_cast<const int4*>(cap + idx * 4);
            c_lg  = logits[idx];
            c_lgl = legal[idx];
        }
        if (t < G) c_gx = g_gxor[gp[b] + t];
    }

    int p = 0;
    for (; b < B; b += gridDim.x) {
        __syncthreads();   // A: previous phase-3 done with shared

        // ---- prefetch board b + gridDim.x ----
        const int nb = b + gridDim.x;
        int  n_pl = 0, n_ch = 0, n_mc = 0, n_h = 0, n_lgl = 0, n_gx = 0;
        float n_lg = 0.0f;
        int4  n_c4 = make_int4(-1, -1, -1, -1);
        if (nb < B) {
            n_pl = player[nb]; n_ch = cur_hash[nb]; n_mc = move_count[nb];
            const size_t nidx = (size_t)nb * N2 + t;
            if (t < N2) {
                n_h   = hist[nidx];
                n_c4  = *reinterpret_cast<const int4*>(cap + nidx * 4);
                n_lg  = logits[nidx];
                n_lgl = legal[nidx];
            }
            if (t < G) n_gx = g_gxor[gp[nb] + t];
        }

        // ---- phase 2a: publish shared state + table insert pass 1 ----
        int mc = c_mc; if (mc < 0) mc = 0; if (mc > N2) mc = N2;
        if (t < N2)   sh_hist[t] = c_h;
        if (t < G)    sh_gx[t]   = c_gx;
        for (int i = t; i < TSLOTS; i += NTHR) sh_tab[1 - p][i] = -1;  // for next iter
        if (t == 0)   sh_ovf_n[1 - p] = 0;

        int      key = 0;
        bool     ins = false;
        unsigned h   = 0;
        int      s1  = 0;
        if (t < N2) {
            if (t < mc)       { key = c_h;      ins = true; }
            else if (t == mc) { key = I32MIN_V; ins = true; }  // sentinel (mc < N2 here)
        }
        if (ins) {
            h  = (unsigned)key * 2654435761u;
            s1 = (int)(h >> 22);                 // 10 bits
            sh_tab[p][s1] = key;                 // plain STS, collisions overwrite
        }
        __syncthreads();   // C: pass-1 writes visible

        // ---- phase 2b: readback; evicted keys take slot2 via CAS, else overflow ----
        if (ins && sh_tab[p][s1] != key) {
            const int s2 = (int)((h >> 12) & (TSLOTS - 1));
            if (atomicCAS(&sh_tab[p][s2], -1, key) != -1) {
                const int oi = atomicAdd(&sh_ovf_n[p], 1);
                if (oi < OVF_CAP) sh_ovf[p][oi] = key;
            }
        }
        __syncthreads();   // B: table complete

        // ---- phase 3: candidate + exact membership + output ----
        if (t < N2) {
            int cd = 0, c;
            c = c_c4.x; if (c >= 0) cd ^= sh_gx[c & (GX - 1)];
            c = c_c4.y; if (c >= 0) cd ^= sh_gx[c & (GX - 1)];
            c = c_c4.z; if (c >= 0) cd ^= sh_gx[c & (GX - 1)];
            c = c_c4.w; if (c >= 0) cd ^= sh_gx[c & (GX - 1)];

            const int cand = c_ch ^ ((c_pl == 0) ? zd_b : zd_w) ^ cd;

            const unsigned hh = (unsigned)cand * 2654435761u;
            bool rep = (sh_tab[p][hh >> 22] == cand) |
                       (sh_tab[p][(hh >> 12) & (TSLOTS - 1)] == cand);

            const int no = sh_ovf_n[p];
            if (no > OVF_CAP) {
                // safety fallback (statistically unreachable): exact scan
                if (mc < N2 && cand == I32MIN_V) rep = true;
                for (int j = 0; j < mc; ++j)
                    if (sh_hist[j] == cand) { rep = true; break; }
            } else {
                for (int i = 0; i < no; ++i) rep |= (sh_ovf[p][i] == cand);
            }

            out[(size_t)b * N2 + t] = ((c_lgl != 0) & !rep) ? c_lg : NEGV;
        }

        // rotate pipeline
        c_pl = n_pl; c_ch = n_ch; c_mc = n_mc; c_h = n_h;
        c_lgl = n_lgl; c_gx = n_gx; c_lg = n_lg; c_c4 = n_c4;
        p ^= 1;
    }
}

extern "C" void kernel_launch(void* const* d_in, const int* in_sizes, int n_in,
                              void* d_out, int out_size)
{
    const float* logits = (const float*)d_in[0];
    const int*   legal  = (const int*)d_in[1];
    const int*   player = (const int*)d_in[2];
    const int*   chash  = (const int*)d_in[3];
    const int*   hist   = (const int*)d_in[4];
    const int*   mcnt   = (const int*)d_in[5];
    const int*   zpos   = (const int*)d_in[6];
    const int*   sgi    = (const int*)d_in[7];
    const int*   sp     = (const int*)d_in[8];
    const int*   gp     = (const int*)d_in[9];
    const int*   cap    = (const int*)d_in[10];
    float*       out    = (float*)d_out;

    const int B = in_sizes[2];           // current_player: B elements
    const int R = in_sizes[8] - 1;       // stone_global_pointer: R+1
    const int G = R / B;                 // groups per board (uniform)

    group_xor_kernel<<<(R + 255) / 256, 256>>>(player, sgi, sp, zpos, R, G);
    board_kernel<<<GRID2, NTHR>>>(logits, legal, player, chash, hist, mcnt,
                                  zpos, gp, cap, out, B, G);
}